// round 8
// baseline (speedup 1.0000x reference)
#include <cuda_runtime.h>
#include <math.h>
#include <stdint.h>

#define EMB 1024
#define SEQ 1024
#define NB 8
#define HEADS 16
#define HD 64
#define ROWS (NB * SEQ)                  // 8192
#define OUT_ELEMS ((size_t)ROWS * EMB)   // 8388608

// Scratch (static device globals; no runtime allocation allowed)
__device__ float g_Q[ROWS * EMB];
__device__ float g_K[ROWS * EMB];
__device__ float g_V[ROWS * EMB];
__device__ float g_O[ROWS * EMB];

// ---------------------------------------------------------------------------
// TF32 helpers
// ---------------------------------------------------------------------------
__device__ __forceinline__ unsigned f2tf(float x) {
    unsigned r;
    asm("cvt.rna.tf32.f32 %0, %1;" : "=r"(r) : "f"(x));
    return r;
}

__device__ __forceinline__ void mma_tf32(float* c, const unsigned* a, const unsigned* b) {
    asm volatile(
        "mma.sync.aligned.m16n8k8.row.col.f32.tf32.tf32.f32 "
        "{%0,%1,%2,%3},{%4,%5,%6,%7},{%8,%9},{%0,%1,%2,%3};\n"
        : "+f"(c[0]), "+f"(c[1]), "+f"(c[2]), "+f"(c[3])
        : "r"(a[0]), "r"(a[1]), "r"(a[2]), "r"(a[3]),
          "r"(b[0]), "r"(b[1]));
}

// ---------------------------------------------------------------------------
// NT GEMM core: C = alpha * A(row-major,lda) @ B(row-major,ldb)^T + bias
// CTA 128x128, 128 threads (4 warps), warp tile 64x64, BK=16 double-buffered.
// smem k-major [k][mn], stride 136 words (conflict-free frag LDS + STS).
// STREAM=1 -> __stcs epilogue stores (no-reuse output streams).
// ---------------------------------------------------------------------------
template <int KDIM, int STREAM>
__device__ __forceinline__ void gemm_nt_body(
    const float* __restrict__ A, int lda,
    const float* __restrict__ B, int ldb,
    float* __restrict__ C, int ldc,
    float alpha, const float* __restrict__ bias)
{
    __shared__ unsigned As[2][16][136];
    __shared__ unsigned Bs[2][16][136];

    const int tid  = threadIdx.x;
    const int m0   = blockIdx.y * 128;
    const int n0   = blockIdx.x * 128;
    const int warp = tid >> 5;
    const int lane = tid & 31;
    const int wr   = (warp >> 1) * 64;
    const int wc   = (warp & 1) * 64;
    const int g    = lane >> 2;
    const int t    = lane & 3;

    const int rowA = tid & 63;
    const int kc   = (tid >> 6) * 8;

    float acc[4][8][4] = {};

    const float* Ap = A + (size_t)(m0 + rowA) * lda + kc;
    const float* Bp = B + (size_t)(n0 + rowA) * ldb + kc;

    float4 av[2][2], bv[2][2];

    auto ldtile = [&](int kt) {
#pragma unroll
        for (int r = 0; r < 2; r++)
#pragma unroll
            for (int h = 0; h < 2; h++) {
                av[r][h] = *(const float4*)(Ap + (size_t)r * 64 * lda + kt * 16 + h * 4);
                bv[r][h] = *(const float4*)(Bp + (size_t)r * 64 * ldb + kt * 16 + h * 4);
            }
    };
    auto sttile = [&](int buf) {
#pragma unroll
        for (int r = 0; r < 2; r++)
#pragma unroll
            for (int h = 0; h < 2; h++) {
                const float* a4 = (const float*)&av[r][h];
                const float* b4 = (const float*)&bv[r][h];
#pragma unroll
                for (int j = 0; j < 4; j++) {
                    As[buf][kc + h * 4 + j][rowA + r * 64] = f2tf(a4[j]);
                    Bs[buf][kc + h * 4 + j][rowA + r * 64] = f2tf(b4[j]);
                }
            }
    };

    ldtile(0);
    sttile(0);
    __syncthreads();

    const int NT = KDIM / 16;
#pragma unroll 1
    for (int kt = 0; kt < NT; kt++) {
        const int buf = kt & 1;
        if (kt + 1 < NT) ldtile(kt + 1);

#pragma unroll
        for (int kk = 0; kk < 16; kk += 8) {
            unsigned af[4][4], bf[8][2];
#pragma unroll
            for (int mi = 0; mi < 4; mi++) {
                af[mi][0] = As[buf][kk + t    ][wr + mi * 16 + g    ];
                af[mi][1] = As[buf][kk + t    ][wr + mi * 16 + g + 8];
                af[mi][2] = As[buf][kk + t + 4][wr + mi * 16 + g    ];
                af[mi][3] = As[buf][kk + t + 4][wr + mi * 16 + g + 8];
            }
#pragma unroll
            for (int ni = 0; ni < 8; ni++) {
                bf[ni][0] = Bs[buf][kk + t    ][wc + ni * 8 + g];
                bf[ni][1] = Bs[buf][kk + t + 4][wc + ni * 8 + g];
            }
#pragma unroll
            for (int mi = 0; mi < 4; mi++)
#pragma unroll
                for (int ni = 0; ni < 8; ni++)
                    mma_tf32(acc[mi][ni], af[mi], bf[ni]);
        }

        if (kt + 1 < NT) sttile(buf ^ 1);
        __syncthreads();
    }

#pragma unroll
    for (int mi = 0; mi < 4; mi++) {
#pragma unroll
        for (int ni = 0; ni < 8; ni++) {
            const int row = m0 + wr + mi * 16 + g;
            const int col = n0 + wc + ni * 8 + t * 2;
            float b0 = 0.f, b1 = 0.f;
            if (bias) { b0 = bias[col]; b1 = bias[col + 1]; }
            float2 v0 = make_float2(acc[mi][ni][0] * alpha + b0, acc[mi][ni][1] * alpha + b1);
            float2 v1 = make_float2(acc[mi][ni][2] * alpha + b0, acc[mi][ni][3] * alpha + b1);
            if (STREAM) {
                __stcs((float2*)&C[(size_t)row * ldc + col], v0);
                __stcs((float2*)&C[(size_t)(row + 8) * ldc + col], v1);
            } else {
                *(float2*)&C[(size_t)row * ldc + col] = v0;
                *(float2*)&C[(size_t)(row + 8) * ldc + col] = v1;
            }
        }
    }
}

// Fused Q/K/V projections: grid.z selects which of the three GEMMs.
__global__ __launch_bounds__(128, 2) void qkv_proj(
    const float* __restrict__ query, const float* __restrict__ key_,
    const float* __restrict__ value,
    const float* __restrict__ Wq, const float* __restrict__ Wk,
    const float* __restrict__ Wv)
{
    const int z = blockIdx.z;
    const float* A = (z == 0) ? query : (z == 1) ? key_ : value;
    const float* W = (z == 0) ? Wq : (z == 1) ? Wk : Wv;
    float* C = (z == 0) ? g_Q : (z == 1) ? g_K : g_V;
    gemm_nt_body<EMB, 0>(A, EMB, W, EMB, C, EMB, 1.0f, nullptr);
}

// Output projection: out = g_O @ Wo^T + bo
__global__ __launch_bounds__(128, 2) void proj_tf32(
    const float* __restrict__ A, const float* __restrict__ B,
    float* __restrict__ C, const float* __restrict__ bias)
{
    gemm_nt_body<EMB, 0>(A, EMB, B, EMB, C, EMB, 1.0f, bias);
}

// att[z,q,k] = 0.125 * Q[n,q,h,:] . K[n,k,h,:]  (z = n*16+h), K-dim = 64
// Streaming stores: 536MB output with no L2 reuse.
__global__ __launch_bounds__(128, 2) void energy_tf32(float* __restrict__ att)
{
    const int z = blockIdx.z;
    const int n = z >> 4, h = z & 15;
    gemm_nt_body<HD, 1>(g_Q + (size_t)n * SEQ * EMB + h * HD, EMB,
                        g_K + (size_t)n * SEQ * EMB + h * HD, EMB,
                        att + (size_t)z * SEQ * SEQ, SEQ, 0.125f, nullptr);
}

// ---------------------------------------------------------------------------
// Fused softmax + att@V.  Per z = n*16+h, m-tile of 128 q-rows:
//   pass 1: per-row max m and 1/sum(exp) over raw energy row (mask applied)
//   pass 2: attv mainloop; staging converts raw energy e -> P = exp(e-m)/l,
//           writes normalized P back to att (__stcs), feeds tf32 MMA.
// C[128,64] = P[128,1024] @ V[1024,64].
// ---------------------------------------------------------------------------
__global__ __launch_bounds__(128, 2) void attv_fused(
    float* __restrict__ att, const int* __restrict__ mask)
{
    const int z = blockIdx.z;
    const int n = z >> 4, h = z & 15;
    float* A = att + (size_t)z * SEQ * SEQ;          // raw energy in, P out
    const float* B = g_V + (size_t)n * SEQ * EMB + h * HD;
    float* C = g_O + (size_t)n * SEQ * EMB + h * HD;
    const int* mrow = mask + n * SEQ;

    __shared__ unsigned As[2][16][136];
    __shared__ unsigned Bs[2][16][72];
    __shared__ float sm_m[128];
    __shared__ float sm_li[128];

    const int tid  = threadIdx.x;
    const int m0   = blockIdx.y * 128;
    const int warp = tid >> 5;
    const int lane = tid & 31;

    // ---- pass 1: row stats (warp per row, 32 rows per warp) ----
    {
        int4 mk[8];
#pragma unroll
        for (int c = 0; c < 8; c++)
            mk[c] = *(const int4*)(mrow + lane * 4 + c * 128);

#pragma unroll 1
        for (int i = 0; i < 32; i++) {
            const int r = warp * 32 + i;
            const float* rp = A + (size_t)(m0 + r) * SEQ;
            float4 xv[8];
            float mx = -3.4e38f;
#pragma unroll
            for (int c = 0; c < 8; c++) {
                xv[c] = *(const float4*)(rp + lane * 4 + c * 128);
                if (mk[c].x == 0) xv[c].x = -1e20f;
                if (mk[c].y == 0) xv[c].y = -1e20f;
                if (mk[c].z == 0) xv[c].z = -1e20f;
                if (mk[c].w == 0) xv[c].w = -1e20f;
                mx = fmaxf(mx, fmaxf(fmaxf(xv[c].x, xv[c].y), fmaxf(xv[c].z, xv[c].w)));
            }
#pragma unroll
            for (int o = 16; o; o >>= 1) mx = fmaxf(mx, __shfl_xor_sync(0xffffffffu, mx, o));
            float s = 0.f;
#pragma unroll
            for (int c = 0; c < 8; c++)
                s += (__expf(xv[c].x - mx) + __expf(xv[c].y - mx)) +
                     (__expf(xv[c].z - mx) + __expf(xv[c].w - mx));
#pragma unroll
            for (int o = 16; o; o >>= 1) s += __shfl_xor_sync(0xffffffffu, s, o);
            if (lane == 0) { sm_m[r] = mx; sm_li[r] = 1.0f / s; }
        }
    }
    __syncthreads();

    // ---- pass 2: attv with on-the-fly P ----
    const int wr   = (warp >> 1) * 64;
    const int wc   = (warp & 1) * 32;
    const int g    = lane >> 2;
    const int t    = lane & 3;

    const int rowA = tid & 63;
    const int kc   = (tid >> 6) * 8;
    const int krow = tid >> 3;
    const int ncol = (tid & 7) * 8;

    float acc[4][4][4] = {};

    const float* Ap = A + (size_t)(m0 + rowA) * SEQ + kc;
    const float* Bp = B + (size_t)krow * EMB + ncol;

    float4 av[2][2], bvv[2];

    auto ldtile = [&](int kt) {
#pragma unroll
        for (int r = 0; r < 2; r++)
#pragma unroll
            for (int h2 = 0; h2 < 2; h2++)
                av[r][h2] = *(const float4*)(Ap + (size_t)r * 64 * SEQ + kt * 16 + h2 * 4);
        bvv[0] = *(const float4*)(Bp + (size_t)kt * 16 * EMB);
        bvv[1] = *(const float4*)(Bp + (size_t)kt * 16 * EMB + 4);
    };
    // convert raw energy -> normalized P, stage tf32 to smem, write P to gmem
    auto sttile = [&](int buf, int kt) {
#pragma unroll
        for (int r = 0; r < 2; r++) {
            const float mr = sm_m[rowA + r * 64];
            const float li = sm_li[rowA + r * 64];
#pragma unroll
            for (int h2 = 0; h2 < 2; h2++) {
                const int col = kt * 16 + kc + h2 * 4;
                const int4 mq = *(const int4*)(mrow + col);
                const float* a4 = (const float*)&av[r][h2];
                float4 p;
                p.x = __expf(((mq.x != 0) ? a4[0] : -1e20f) - mr) * li;
                p.y = __expf(((mq.y != 0) ? a4[1] : -1e20f) - mr) * li;
                p.z = __expf(((mq.z != 0) ? a4[2] : -1e20f) - mr) * li;
                p.w = __expf(((mq.w != 0) ? a4[3] : -1e20f) - mr) * li;
                As[buf][kc + h2 * 4 + 0][rowA + r * 64] = f2tf(p.x);
                As[buf][kc + h2 * 4 + 1][rowA + r * 64] = f2tf(p.y);
                As[buf][kc + h2 * 4 + 2][rowA + r * 64] = f2tf(p.z);
                As[buf][kc + h2 * 4 + 3][rowA + r * 64] = f2tf(p.w);
                __stcs((float4*)(A + (size_t)(m0 + rowA + r * 64) * SEQ + col), p);
            }
        }
        const float* b8 = (const float*)bvv;
#pragma unroll
        for (int j = 0; j < 8; j++)
            Bs[buf][krow][ncol + j] = f2tf(b8[j]);
    };

    ldtile(0);
    sttile(0, 0);
    __syncthreads();

    const int NT = SEQ / 16;
#pragma unroll 1
    for (int kt = 0; kt < NT; kt++) {
        const int buf = kt & 1;
        if (kt + 1 < NT) ldtile(kt + 1);

#pragma unroll
        for (int kk = 0; kk < 16; kk += 8) {
            unsigned af[4][4], bf[4][2];
#pragma unroll
            for (int mi = 0; mi < 4; mi++) {
                af[mi][0] = As[buf][kk + t    ][wr + mi * 16 + g    ];
                af[mi][1] = As[buf][kk + t    ][wr + mi * 16 + g + 8];
                af[mi][2] = As[buf][kk + t + 4][wr + mi * 16 + g    ];
                af[mi][3] = As[buf][kk + t + 4][wr + mi * 16 + g + 8];
            }
#pragma unroll
            for (int ni = 0; ni < 4; ni++) {
                bf[ni][0] = Bs[buf][kk + t    ][wc + ni * 8 + g];
                bf[ni][1] = Bs[buf][kk + t + 4][wc + ni * 8 + g];
            }
#pragma unroll
            for (int mi = 0; mi < 4; mi++)
#pragma unroll
                for (int ni = 0; ni < 4; ni++)
                    mma_tf32(acc[mi][ni], af[mi], bf[ni]);
        }

        if (kt + 1 < NT) sttile(buf ^ 1, kt + 1);
        __syncthreads();
    }

#pragma unroll
    for (int mi = 0; mi < 4; mi++) {
#pragma unroll
        for (int ni = 0; ni < 4; ni++) {
            const int row = m0 + wr + mi * 16 + g;
            const int col = wc + ni * 8 + t * 2;
            *(float2*)&C[(size_t)row * EMB + col] =
                make_float2(acc[mi][ni][0], acc[mi][ni][1]);
            *(float2*)&C[(size_t)(row + 8) * EMB + col] =
                make_float2(acc[mi][ni][2], acc[mi][ni][3]);
        }
    }
}

// ---------------------------------------------------------------------------
extern "C" void kernel_launch(void* const* d_in, const int* in_sizes, int n_in,
                              void* d_out, int out_size)
{
    const float* value = (const float*)d_in[0];
    const float* key_  = (const float*)d_in[1];
    const float* query = (const float*)d_in[2];
    const int*   mask  = (const int*)d_in[3];
    const float* Wv    = (const float*)d_in[4];
    const float* Wk    = (const float*)d_in[5];
    const float* Wq    = (const float*)d_in[6];
    const float* Wo    = (const float*)d_in[7];
    const float* bo    = (const float*)d_in[8];

    float* out = (float*)d_out;                 // [8,1024,1024]
    float* att = out + OUT_ELEMS;               // [8,16,1024,1024]

    float* op;
    cudaGetSymbolAddress((void**)&op, g_O);

    dim3 blk(128);

    qkv_proj<<<dim3(EMB / 128, ROWS / 128, 3), blk>>>(query, key_, value, Wq, Wk, Wv);
    energy_tf32<<<dim3(SEQ / 128, SEQ / 128, NB * HEADS), blk>>>(att);
    attv_fused<<<dim3(1, SEQ / 128, NB * HEADS), blk>>>(att, mask);
    proj_tf32<<<dim3(EMB / 128, ROWS / 128), blk>>>(op, Wo, out, bo);
}

// round 12
// speedup vs baseline: 1.1199x; 1.1199x over previous
#include <cuda_runtime.h>
#include <math.h>
#include <stdint.h>

#define EMB 1024
#define SEQ 1024
#define NB 8
#define HEADS 16
#define HD 64
#define ROWS (NB * SEQ)                  // 8192
#define OUT_ELEMS ((size_t)ROWS * EMB)   // 8388608
#define SROW 20                          // smem words per row (80B, 16B-aligned)

// Scratch (static device globals; no runtime allocation allowed)
__device__ float g_Q[ROWS * EMB];
__device__ float g_K[ROWS * EMB];
__device__ float g_V[ROWS * EMB];
__device__ float g_O[ROWS * EMB];

// ---------------------------------------------------------------------------
// helpers
// ---------------------------------------------------------------------------
__device__ __forceinline__ unsigned f2tf(float x) {
    unsigned r;
    asm("cvt.rna.tf32.f32 %0, %1;" : "=r"(r) : "f"(x));
    return r;
}

__device__ __forceinline__ void mma_tf32(float* c, const unsigned* a, const unsigned* b) {
    asm volatile(
        "mma.sync.aligned.m16n8k8.row.col.f32.tf32.tf32.f32 "
        "{%0,%1,%2,%3},{%4,%5,%6,%7},{%8,%9},{%0,%1,%2,%3};\n"
        : "+f"(c[0]), "+f"(c[1]), "+f"(c[2]), "+f"(c[3])
        : "r"(a[0]), "r"(a[1]), "r"(a[2]), "r"(a[3]),
          "r"(b[0]), "r"(b[1]));
}

__device__ __forceinline__ uint32_t smem_u32(const void* p) {
    uint32_t a;
    asm("{ .reg .u64 t; cvta.to.shared.u64 t, %1; cvt.u32.u64 %0, t; }"
        : "=r"(a) : "l"(p));
    return a;
}

__device__ __forceinline__ void ldsm4(unsigned& r0, unsigned& r1, unsigned& r2,
                                      unsigned& r3, uint32_t addr) {
    asm volatile("ldmatrix.sync.aligned.m8n8.x4.shared.b16 {%0,%1,%2,%3}, [%4];"
                 : "=r"(r0), "=r"(r1), "=r"(r2), "=r"(r3) : "r"(addr));
}

// byte offset of the 16B chunk jc (tf32 cols jc*4..jc*4+3) of row `row`
__device__ __forceinline__ uint32_t frag_off(int row, int jc) {
    const int chunk = jc ^ ((row >> 3) & 3);
    return (uint32_t)((row * SROW + chunk * 4) * 4);
}

// ---------------------------------------------------------------------------
// NT GEMM: C = alpha * A(row-major,lda) @ B(row-major,ldb)^T + bias
// CTA 128x128, 128 thr (4 warps), warp tile 64x64, BK=16 double-buffered.
// smem row-major [row][k] (stride SROW, XOR 16B-chunk swizzle); fragments
// loaded with ldmatrix.x4 (conflict-free).
// ---------------------------------------------------------------------------
template <int KDIM>
__device__ __forceinline__ void gemm_nt_body(
    const float* __restrict__ A, int lda,
    const float* __restrict__ B, int ldb,
    float* __restrict__ C, int ldc,
    float alpha, const float* __restrict__ bias)
{
    __shared__ unsigned As[2][128 * SROW];
    __shared__ unsigned Bs[2][128 * SROW];

    const int tid  = threadIdx.x;
    const int m0   = blockIdx.y * 128;
    const int n0   = blockIdx.x * 128;
    const int warp = tid >> 5;
    const int lane = tid & 31;
    const int wr   = (warp >> 1) * 64;
    const int wc   = (warp & 1) * 64;
    const int g    = lane >> 2;
    const int t    = lane & 3;

    const uint32_t abase[2] = { smem_u32(&As[0][0]), smem_u32(&As[1][0]) };
    const uint32_t bbase[2] = { smem_u32(&Bs[0][0]), smem_u32(&Bs[1][0]) };

    // per-lane ldmatrix pointer offsets (loop-invariant)
    const int lrow8 = ((lane >> 3) & 1) * 8 + (lane & 7);
    const int ljc   = lane >> 4;                     // 0 or 1
    uint32_t aoff[2][4], boff[2][4];
#pragma unroll
    for (int kkc = 0; kkc < 2; kkc++)
#pragma unroll
        for (int i = 0; i < 4; i++) {
            aoff[kkc][i] = frag_off(wr + i * 16 + lrow8, kkc * 2 + ljc);
            boff[kkc][i] = frag_off(wc + i * 16 + lrow8, kkc * 2 + ljc);
        }

    float acc[4][8][4] = {};

    const int srow = tid;                            // staging row 0..127
    const float* Ap = A + (size_t)(m0 + srow) * lda;
    const float* Bp = B + (size_t)(n0 + srow) * ldb;
    const int schunkx = (srow >> 3) & 3;

    float4 av[4], bv[4];
    auto ldtile = [&](int kt) {
#pragma unroll
        for (int j = 0; j < 4; j++) {
            av[j] = *(const float4*)(Ap + kt * 16 + j * 4);
            bv[j] = *(const float4*)(Bp + kt * 16 + j * 4);
        }
    };
    auto sttile = [&](int buf) {
#pragma unroll
        for (int j = 0; j < 4; j++) {
            const int chunk = j ^ schunkx;
            uint4 at = make_uint4(f2tf(av[j].x), f2tf(av[j].y), f2tf(av[j].z), f2tf(av[j].w));
            uint4 bt = make_uint4(f2tf(bv[j].x), f2tf(bv[j].y), f2tf(bv[j].z), f2tf(bv[j].w));
            *(uint4*)&As[buf][srow * SROW + chunk * 4] = at;
            *(uint4*)&Bs[buf][srow * SROW + chunk * 4] = bt;
        }
    };

    ldtile(0);
    sttile(0);
    __syncthreads();

    const int NT = KDIM / 16;
#pragma unroll 1
    for (int kt = 0; kt < NT; kt++) {
        const int buf = kt & 1;
        if (kt + 1 < NT) ldtile(kt + 1);

#pragma unroll
        for (int kkc = 0; kkc < 2; kkc++) {
            unsigned af[4][4], bf[8][2];
#pragma unroll
            for (int mi = 0; mi < 4; mi++)
                ldsm4(af[mi][0], af[mi][1], af[mi][2], af[mi][3],
                      abase[buf] + aoff[kkc][mi]);
#pragma unroll
            for (int p = 0; p < 4; p++) {
                unsigned r0, r1, r2, r3;
                ldsm4(r0, r1, r2, r3, bbase[buf] + boff[kkc][p]);
                bf[2 * p][0] = r0; bf[2 * p + 1][0] = r1;
                bf[2 * p][1] = r2; bf[2 * p + 1][1] = r3;
            }
#pragma unroll
            for (int mi = 0; mi < 4; mi++)
#pragma unroll
                for (int ni = 0; ni < 8; ni++)
                    mma_tf32(acc[mi][ni], af[mi], bf[ni]);
        }

        if (kt + 1 < NT) sttile(buf ^ 1);
        __syncthreads();
    }

#pragma unroll
    for (int mi = 0; mi < 4; mi++) {
#pragma unroll
        for (int ni = 0; ni < 8; ni++) {
            const int row = m0 + wr + mi * 16 + g;
            const int col = n0 + wc + ni * 8 + t * 2;
            float b0 = 0.f, b1 = 0.f;
            if (bias) { b0 = bias[col]; b1 = bias[col + 1]; }
            *(float2*)&C[(size_t)row * ldc + col] =
                make_float2(acc[mi][ni][0] * alpha + b0, acc[mi][ni][1] * alpha + b1);
            *(float2*)&C[(size_t)(row + 8) * ldc + col] =
                make_float2(acc[mi][ni][2] * alpha + b0, acc[mi][ni][3] * alpha + b1);
        }
    }
}

// Fused Q/K/V projections: grid.z selects which GEMM.
__global__ __launch_bounds__(128, 2) void qkv_proj(
    const float* __restrict__ query, const float* __restrict__ key_,
    const float* __restrict__ value,
    const float* __restrict__ Wq, const float* __restrict__ Wk,
    const float* __restrict__ Wv)
{
    const int z = blockIdx.z;
    const float* A = (z == 0) ? query : (z == 1) ? key_ : value;
    const float* W = (z == 0) ? Wq : (z == 1) ? Wk : Wv;
    float* C = (z == 0) ? g_Q : (z == 1) ? g_K : g_V;
    gemm_nt_body<EMB>(A, EMB, W, EMB, C, EMB, 1.0f, nullptr);
}

__global__ __launch_bounds__(128, 2) void proj_tf32(
    const float* __restrict__ A, const float* __restrict__ B,
    float* __restrict__ C, const float* __restrict__ bias)
{
    gemm_nt_body<EMB>(A, EMB, B, EMB, C, EMB, 1.0f, bias);
}

__global__ __launch_bounds__(128, 2) void energy_tf32(float* __restrict__ att)
{
    const int z = blockIdx.z;
    const int n = z >> 4, h = z & 15;
    gemm_nt_body<HD>(g_Q + (size_t)n * SEQ * EMB + h * HD, EMB,
                     g_K + (size_t)n * SEQ * EMB + h * HD, EMB,
                     att + (size_t)z * SEQ * SEQ, SEQ, 0.125f, nullptr);
}

// ---------------------------------------------------------------------------
// Row softmax over last dim (1024), in place, with mask[n,k] (-1e20 where 0).
// ---------------------------------------------------------------------------
__global__ __launch_bounds__(256) void softmax_kernel(
    float* __restrict__ att, const int* __restrict__ mask)
{
    __shared__ float sbuf[8];
    const int row = blockIdx.x;
    const int n = row >> 14;
    float* p = att + (size_t)row * SEQ;
    const int c = threadIdx.x * 4;
    const int* mrow = mask + n * SEQ;

    float4 x = *(const float4*)(p + c);
    if (mrow[c + 0] == 0) x.x = -1e20f;
    if (mrow[c + 1] == 0) x.y = -1e20f;
    if (mrow[c + 2] == 0) x.z = -1e20f;
    if (mrow[c + 3] == 0) x.w = -1e20f;

    float m = fmaxf(fmaxf(x.x, x.y), fmaxf(x.z, x.w));
#pragma unroll
    for (int o = 16; o; o >>= 1) m = fmaxf(m, __shfl_xor_sync(0xffffffffu, m, o));
    if ((threadIdx.x & 31) == 0) sbuf[threadIdx.x >> 5] = m;
    __syncthreads();
    m = sbuf[0];
#pragma unroll
    for (int i = 1; i < 8; i++) m = fmaxf(m, sbuf[i]);

    float4 e;
    e.x = __expf(x.x - m);
    e.y = __expf(x.y - m);
    e.z = __expf(x.z - m);
    e.w = __expf(x.w - m);
    float s = (e.x + e.y) + (e.z + e.w);
#pragma unroll
    for (int o = 16; o; o >>= 1) s += __shfl_xor_sync(0xffffffffu, s, o);
    __syncthreads();
    if ((threadIdx.x & 31) == 0) sbuf[threadIdx.x >> 5] = s;
    __syncthreads();
    s = 0.f;
#pragma unroll
    for (int i = 0; i < 8; i++) s += sbuf[i];

    const float inv = 1.0f / s;
    e.x *= inv; e.y *= inv; e.z *= inv; e.w *= inv;
    *(float4*)(p + c) = e;
}

// ---------------------------------------------------------------------------
// att*V (NN): per z = n*16+h,  C[1024,64] = P[1024,1024] @ V[1024,64]
// CTA 128x64, warp tile 64x32. A staged row-major [q][k]; V transposed into
// [n][k] at staging so B fragments also come from ldmatrix.
// ---------------------------------------------------------------------------
__global__ __launch_bounds__(128, 2) void attv_tf32(const float* __restrict__ att)
{
    const int z = blockIdx.z;
    const int n = z >> 4, h = z & 15;
    const float* A = att + (size_t)z * SEQ * SEQ;
    const float* B = g_V + (size_t)n * SEQ * EMB + h * HD;
    float* C = g_O + (size_t)n * SEQ * EMB + h * HD;

    __shared__ unsigned As[2][128 * SROW];
    __shared__ unsigned Bs[2][64 * SROW];

    const int tid  = threadIdx.x;
    const int m0   = blockIdx.y * 128;
    const int warp = tid >> 5;
    const int lane = tid & 31;
    const int wr   = (warp >> 1) * 64;
    const int wc   = (warp & 1) * 32;
    const int g    = lane >> 2;
    const int t    = lane & 3;

    const uint32_t abase[2] = { smem_u32(&As[0][0]), smem_u32(&As[1][0]) };
    const uint32_t bbase[2] = { smem_u32(&Bs[0][0]), smem_u32(&Bs[1][0]) };

    const int lrow8 = ((lane >> 3) & 1) * 8 + (lane & 7);
    const int ljc   = lane >> 4;
    uint32_t aoff[2][4], boff[2][2];
#pragma unroll
    for (int kkc = 0; kkc < 2; kkc++) {
#pragma unroll
        for (int i = 0; i < 4; i++)
            aoff[kkc][i] = frag_off(wr + i * 16 + lrow8, kkc * 2 + ljc);
#pragma unroll
        for (int p = 0; p < 2; p++)
            boff[kkc][p] = frag_off(wc + p * 16 + lrow8, kkc * 2 + ljc);
    }

    float acc[4][4][4] = {};

    const int srow = tid;
    const float* Ap = A + (size_t)(m0 + srow) * SEQ;
    const int schunkx = (srow >> 3) & 3;
    // B staging: 2 float4 per thread; k = bk (+8), n cols bnc..bnc+3
    const int bk  = tid >> 4;            // 0..7
    const int bnc = (tid & 15) * 4;      // 0..60

    float4 av[4], bvv[2];
    auto ldtile = [&](int kt) {
#pragma unroll
        for (int j = 0; j < 4; j++)
            av[j] = *(const float4*)(Ap + kt * 16 + j * 4);
#pragma unroll
        for (int i = 0; i < 2; i++)
            bvv[i] = *(const float4*)(B + (size_t)(kt * 16 + bk + i * 8) * EMB + bnc);
    };
    auto sttile = [&](int buf) {
#pragma unroll
        for (int j = 0; j < 4; j++) {
            const int chunk = j ^ schunkx;
            uint4 at = make_uint4(f2tf(av[j].x), f2tf(av[j].y), f2tf(av[j].z), f2tf(av[j].w));
            *(uint4*)&As[buf][srow * SROW + chunk * 4] = at;
        }
#pragma unroll
        for (int i = 0; i < 2; i++) {
            const int k = bk + i * 8;
            const int jc = k >> 2, kw = k & 3;
            const float* v4 = (const float*)&bvv[i];
#pragma unroll
            for (int c = 0; c < 4; c++) {
                const int nrow = bnc + c;
                const int chunk = jc ^ ((nrow >> 3) & 3);
                Bs[buf][nrow * SROW + chunk * 4 + kw] = f2tf(v4[c]);
            }
        }
    };

    ldtile(0);
    sttile(0);
    __syncthreads();

    const int NT = SEQ / 16;
#pragma unroll 1
    for (int kt = 0; kt < NT; kt++) {
        const int buf = kt & 1;
        if (kt + 1 < NT) ldtile(kt + 1);

#pragma unroll
        for (int kkc = 0; kkc < 2; kkc++) {
            unsigned af[4][4], bf[4][2];
#pragma unroll
            for (int mi = 0; mi < 4; mi++)
                ldsm4(af[mi][0], af[mi][1], af[mi][2], af[mi][3],
                      abase[buf] + aoff[kkc][mi]);
#pragma unroll
            for (int p = 0; p < 2; p++) {
                unsigned r0, r1, r2, r3;
                ldsm4(r0, r1, r2, r3, bbase[buf] + boff[kkc][p]);
                bf[2 * p][0] = r0; bf[2 * p + 1][0] = r1;
                bf[2 * p][1] = r2; bf[2 * p + 1][1] = r3;
            }
#pragma unroll
            for (int mi = 0; mi < 4; mi++)
#pragma unroll
                for (int ni = 0; ni < 4; ni++)
                    mma_tf32(acc[mi][ni], af[mi], bf[ni]);
        }

        if (kt + 1 < NT) sttile(buf ^ 1);
        __syncthreads();
    }

#pragma unroll
    for (int mi = 0; mi < 4; mi++) {
#pragma unroll
        for (int ni = 0; ni < 4; ni++) {
            const int row = m0 + wr + mi * 16 + g;
            const int col = wc + ni * 8 + t * 2;
            *(float2*)&C[(size_t)row * EMB + col] =
                make_float2(acc[mi][ni][0], acc[mi][ni][1]);
            *(float2*)&C[(size_t)(row + 8) * EMB + col] =
                make_float2(acc[mi][ni][2], acc[mi][ni][3]);
        }
    }
}

// ---------------------------------------------------------------------------
extern "C" void kernel_launch(void* const* d_in, const int* in_sizes, int n_in,
                              void* d_out, int out_size)
{
    const float* value = (const float*)d_in[0];
    const float* key_  = (const float*)d_in[1];
    const float* query = (const float*)d_in[2];
    const int*   mask  = (const int*)d_in[3];
    const float* Wv    = (const float*)d_in[4];
    const float* Wk    = (const float*)d_in[5];
    const float* Wq    = (const float*)d_in[6];
    const float* Wo    = (const float*)d_in[7];
    const float* bo    = (const float*)d_in[8];

    float* out = (float*)d_out;                 // [8,1024,1024]
    float* att = out + OUT_ELEMS;               // [8,16,1024,1024]

    float* op;
    cudaGetSymbolAddress((void**)&op, g_O);

    dim3 blk(128);

    qkv_proj<<<dim3(EMB / 128, ROWS / 128, 3), blk>>>(query, key_, value, Wq, Wk, Wv);
    energy_tf32<<<dim3(SEQ / 128, SEQ / 128, NB * HEADS), blk>>>(att);
    softmax_kernel<<<NB * HEADS * SEQ, 256>>>(att, mask);
    attv_tf32<<<dim3(1, SEQ / 128, NB * HEADS), blk>>>(att);
    proj_tf32<<<dim3(EMB / 128, ROWS / 128), blk>>>(op, Wo, out, bo);
}